// round 6
// baseline (speedup 1.0000x reference)
#include <cuda_runtime.h>
#include <cuda_fp16.h>
#include <cstdint>

#define DIMC 1024
#define HEADS 16
#define DH 64
#define BATCHB 4
#define SEQN 2048
#define SCALE 0.125f
#define LOG2E 1.4426950408889634f

// Scratch (no allocations allowed)
__device__ float g_qkv[(size_t)BATCHB * SEQN * 3 * DIMC];
__device__ float g_x[(size_t)BATCHB * SEQN * DIMC];

// ---------------- small PTX helpers ----------------
__device__ __forceinline__ uint32_t f2tf32(float x) {
    uint32_t r;
    asm("cvt.rna.tf32.f32 %0, %1;" : "=r"(r) : "f"(x));
    return r;
}
__device__ __forceinline__ void mma_tf32(float* d, const uint32_t* a, const uint32_t* b) {
    asm volatile(
        "mma.sync.aligned.m16n8k8.row.col.f32.tf32.tf32.f32 "
        "{%0,%1,%2,%3}, {%4,%5,%6,%7}, {%8,%9}, {%0,%1,%2,%3};"
        : "+f"(d[0]), "+f"(d[1]), "+f"(d[2]), "+f"(d[3])
        : "r"(a[0]), "r"(a[1]), "r"(a[2]), "r"(a[3]),
          "r"(b[0]), "r"(b[1]));
}
__device__ __forceinline__ void mma16816(float* d, const uint32_t* a, uint32_t b0, uint32_t b1) {
    asm volatile(
        "mma.sync.aligned.m16n8k16.row.col.f32.f16.f16.f32 "
        "{%0,%1,%2,%3}, {%4,%5,%6,%7}, {%8,%9}, {%0,%1,%2,%3};"
        : "+f"(d[0]), "+f"(d[1]), "+f"(d[2]), "+f"(d[3])
        : "r"(a[0]), "r"(a[1]), "r"(a[2]), "r"(a[3]),
          "r"(b0), "r"(b1));
}
__device__ __forceinline__ void ldsm_x4_t(uint32_t& r0, uint32_t& r1, uint32_t& r2, uint32_t& r3,
                                          uint32_t addr) {
    asm volatile("ldmatrix.sync.aligned.m8n8.x4.trans.shared.b16 {%0,%1,%2,%3}, [%4];"
                 : "=r"(r0), "=r"(r1), "=r"(r2), "=r"(r3) : "r"(addr));
}
__device__ __forceinline__ float ex2f(float x) {
    float y;
    asm("ex2.approx.ftz.f32 %0, %1;" : "=f"(y) : "f"(x));
    return y;
}
__device__ __forceinline__ uint32_t packh2(float lo, float hi) {
    __half2 h = __floats2half2_rn(lo, hi);
    return *(uint32_t*)&h;
}

// ---------------------------------------------------------------------------
// C[m,n] = sum_k A[m,k]*B[n,k] (+bias).  TF32 MMA, 2-stage smem pipeline.
// Block 128x128, BK=32, 256 threads (8 warps as 2m x 4n), warp tile 64x32.
// Dynamic smem: As[2][128][36] | Bs[2][128][36]  (73728 B)
// ---------------------------------------------------------------------------
#define TILE_U32 (128 * 36)

__global__ __launch_bounds__(256) void gemm_nt_tf32(const float* __restrict__ A,
                                                    const float* __restrict__ B,
                                                    float* __restrict__ C,
                                                    const float* __restrict__ bias,
                                                    int M, int N, int K)
{
    extern __shared__ uint32_t sm[];
    uint32_t* As = sm;                 // [2][128][36]
    uint32_t* Bs = sm + 2 * TILE_U32;  // [2][128][36]

    const int tid  = threadIdx.x;
    const int wid  = tid >> 5;
    const int lane = tid & 31;
    const int g    = lane >> 2;
    const int tg   = lane & 3;
    const int bm   = blockIdx.y * 128;
    const int bn   = blockIdx.x * 128;
    const int wm   = (wid >> 2) * 64;
    const int wn   = (wid & 3) * 32;

    const int lrow = tid >> 3;          // 0..31
    const int lcol = (tid & 7) * 4;     // 0..28

    float acc[4][4][4];
#pragma unroll
    for (int mt = 0; mt < 4; mt++)
#pragma unroll
        for (int nt = 0; nt < 4; nt++)
#pragma unroll
            for (int i = 0; i < 4; i++) acc[mt][nt][i] = 0.0f;

    float4 ra[4], rb[4];
#pragma unroll
    for (int i = 0; i < 4; i++) {
        ra[i] = *(const float4*)(A + (size_t)(bm + lrow + i * 32) * K + lcol);
        rb[i] = *(const float4*)(B + (size_t)(bn + lrow + i * 32) * K + lcol);
    }
    // store chunk 0 into buffer 0
#pragma unroll
    for (int i = 0; i < 4; i++) {
        uint32_t* ap = As + (lrow + i * 32) * 36 + lcol;
        ap[0] = f2tf32(ra[i].x); ap[1] = f2tf32(ra[i].y);
        ap[2] = f2tf32(ra[i].z); ap[3] = f2tf32(ra[i].w);
        uint32_t* bp = Bs + (lrow + i * 32) * 36 + lcol;
        bp[0] = f2tf32(rb[i].x); bp[1] = f2tf32(rb[i].y);
        bp[2] = f2tf32(rb[i].z); bp[3] = f2tf32(rb[i].w);
    }
    __syncthreads();

    for (int k0 = 0; k0 < K; k0 += 32) {
        const int cur = (k0 >> 5) & 1;
        const uint32_t* Ac = As + cur * TILE_U32;
        const uint32_t* Bc = Bs + cur * TILE_U32;
        const bool have_next = (k0 + 32 < K);

        if (have_next) {
#pragma unroll
            for (int i = 0; i < 4; i++) {
                ra[i] = *(const float4*)(A + (size_t)(bm + lrow + i * 32) * K + k0 + 32 + lcol);
                rb[i] = *(const float4*)(B + (size_t)(bn + lrow + i * 32) * K + k0 + 32 + lcol);
            }
        }

#pragma unroll
        for (int ks = 0; ks < 4; ks++) {
            const int kc = ks * 8;
            uint32_t afrag[4][4];
            uint32_t bfrag[4][2];
#pragma unroll
            for (int mt = 0; mt < 4; mt++) {
                int r0 = wm + mt * 16 + g;
                afrag[mt][0] = Ac[r0 * 36 + kc + tg];
                afrag[mt][1] = Ac[(r0 + 8) * 36 + kc + tg];
                afrag[mt][2] = Ac[r0 * 36 + kc + tg + 4];
                afrag[mt][3] = Ac[(r0 + 8) * 36 + kc + tg + 4];
            }
#pragma unroll
            for (int nt = 0; nt < 4; nt++) {
                int c0 = wn + nt * 8 + g;
                bfrag[nt][0] = Bc[c0 * 36 + kc + tg];
                bfrag[nt][1] = Bc[c0 * 36 + kc + tg + 4];
            }
#pragma unroll
            for (int mt = 0; mt < 4; mt++)
#pragma unroll
                for (int nt = 0; nt < 4; nt++)
                    mma_tf32(acc[mt][nt], afrag[mt], bfrag[nt]);
        }

        if (have_next) {
            uint32_t* An = As + (cur ^ 1) * TILE_U32;
            uint32_t* Bn = Bs + (cur ^ 1) * TILE_U32;
#pragma unroll
            for (int i = 0; i < 4; i++) {
                uint32_t* ap = An + (lrow + i * 32) * 36 + lcol;
                ap[0] = f2tf32(ra[i].x); ap[1] = f2tf32(ra[i].y);
                ap[2] = f2tf32(ra[i].z); ap[3] = f2tf32(ra[i].w);
                uint32_t* bp = Bn + (lrow + i * 32) * 36 + lcol;
                bp[0] = f2tf32(rb[i].x); bp[1] = f2tf32(rb[i].y);
                bp[2] = f2tf32(rb[i].z); bp[3] = f2tf32(rb[i].w);
            }
        }
        __syncthreads();
    }

    // Epilogue
#pragma unroll
    for (int mt = 0; mt < 4; mt++) {
#pragma unroll
        for (int nt = 0; nt < 4; nt++) {
            int row0 = bm + wm + mt * 16 + g;
            int col  = bn + wn + nt * 8 + 2 * tg;
            float b0 = 0.0f, b1 = 0.0f;
            if (bias != nullptr) { b0 = bias[col]; b1 = bias[col + 1]; }
            float2 v0, v1;
            v0.x = acc[mt][nt][0] + b0; v0.y = acc[mt][nt][1] + b1;
            v1.x = acc[mt][nt][2] + b0; v1.y = acc[mt][nt][3] + b1;
            *(float2*)(C + (size_t)row0 * N + col)       = v0;
            *(float2*)(C + (size_t)(row0 + 8) * N + col) = v1;
        }
    }
}

// ---------------------------------------------------------------------------
// Flash attention, fp16 MMA, 2-stage KV pipeline.
// Block = (b, h, 128 q-rows). 8 warps x 16 q-rows. 64-key tiles.
// ---------------------------------------------------------------------------
__global__ __launch_bounds__(256, 2) void attn_fa16(const float* __restrict__ qkv,
                                                    const int* __restrict__ pmask,
                                                    float* __restrict__ xout)
{
    __shared__ __half Ks[2][64][72];
    __shared__ __half Vs[2][64][72];
    __shared__ float  mb[2][64];

    const int t    = threadIdx.x;
    const int w    = t >> 5;
    const int lane = t & 31;
    const int g    = lane >> 2;
    const int tg   = lane & 3;
    const int h    = blockIdx.y;
    const int b    = blockIdx.z;
    const int qbase = blockIdx.x * 128;

    const float SC2 = SCALE * LOG2E;

    // ---- Q fragments (registers, whole kernel) ----
    uint32_t qa[4][4];
    {
        const int qr = b * SEQN + qbase + w * 16 + g;
        const float* q0 = qkv + (size_t)qr * (3 * DIMC) + h * DH;
        const float* q8 = q0 + (size_t)8 * (3 * DIMC);
#pragma unroll
        for (int kt = 0; kt < 4; kt++) {
            float2 v0 = *(const float2*)(q0 + kt * 16 + 2 * tg);
            float2 v1 = *(const float2*)(q8 + kt * 16 + 2 * tg);
            float2 v2 = *(const float2*)(q0 + kt * 16 + 8 + 2 * tg);
            float2 v3 = *(const float2*)(q8 + kt * 16 + 8 + 2 * tg);
            qa[kt][0] = packh2(v0.x, v0.y);
            qa[kt][1] = packh2(v1.x, v1.y);
            qa[kt][2] = packh2(v2.x, v2.y);
            qa[kt][3] = packh2(v3.x, v3.y);
        }
    }

    const int lr = ((lane >> 3) & 1) * 8 + (lane & 7);
    const int lc = (lane >> 4) * 8;
    const uint32_t vsmem = (uint32_t)__cvta_generic_to_shared(&Vs[0][0][0]);

    float m0 = -1e30f, m1 = -1e30f, l0 = 0.0f, l1 = 0.0f;
    float of[8][4];
#pragma unroll
    for (int nt = 0; nt < 8; nt++)
#pragma unroll
        for (int i = 0; i < 4; i++) of[nt][i] = 0.0f;

    const int dcol = lane * 2;  // 0..62
    const int krow = w;         // keys w + 8j

    // ---- prologue: stage tile 0 into buffer 0 ----
#pragma unroll
    for (int j = 0; j < 8; j++) {
        const int key = krow + j * 8;
        const float* kp = qkv + (size_t)(b * SEQN + key) * (3 * DIMC) + DIMC + h * DH + dcol;
        float2 kv = *(const float2*)kp;
        float2 vv = *(const float2*)(kp + DIMC);
        *(uint32_t*)&Ks[0][key][dcol] = packh2(kv.x, kv.y);
        *(uint32_t*)&Vs[0][key][dcol] = packh2(vv.x, vv.y);
    }
    if (t < 64) mb[0][t] = (pmask[b * SEQN + t] > 0) ? -1e9f : 0.0f;
    __syncthreads();

    for (int it = 0; it < SEQN / 64; it++) {
        const int cur = it & 1;
        const int nxt = cur ^ 1;
        const int kb_next = (it + 1) * 64;
        const bool have_next = (it < SEQN / 64 - 1);

        // ---- prefetch K(i+1) + mask(i+1) ----
        uint32_t kreg[8];
        float mreg = 0.0f;
        if (have_next) {
#pragma unroll
            for (int j = 0; j < 8; j++) {
                const int key = krow + j * 8;
                const float* kp = qkv + (size_t)(b * SEQN + kb_next + key) * (3 * DIMC) + DIMC + h * DH + dcol;
                float2 kv = *(const float2*)kp;
                kreg[j] = packh2(kv.x, kv.y);
            }
            if (t < 64) mreg = (pmask[b * SEQN + kb_next + t] > 0) ? -1e9f : 0.0f;
        }

        // ---- S = Q K^T on buffer cur ----
        float sf[8][4];
#pragma unroll
        for (int nt = 0; nt < 8; nt++)
#pragma unroll
            for (int i = 0; i < 4; i++) sf[nt][i] = 0.0f;
#pragma unroll
        for (int kt = 0; kt < 4; kt++) {
#pragma unroll
            for (int nt = 0; nt < 8; nt++) {
                uint32_t kb0 = *(const uint32_t*)&Ks[cur][8 * nt + g][16 * kt + 2 * tg];
                uint32_t kb1 = *(const uint32_t*)&Ks[cur][8 * nt + g][16 * kt + 2 * tg + 8];
                mma16816(sf[nt], qa[kt], kb0, kb1);
            }
        }

        // store K(i+1)
        if (have_next) {
#pragma unroll
            for (int j = 0; j < 8; j++)
                *(uint32_t*)&Ks[nxt][krow + j * 8][dcol] = kreg[j];
        }

        // ---- softmax (base-2) ----
        float mt0 = -1e30f, mt1 = -1e30f;
#pragma unroll
        for (int nt = 0; nt < 8; nt++) {
            float2 bb = *(const float2*)&mb[cur][8 * nt + 2 * tg];
            sf[nt][0] = fmaf(sf[nt][0], SC2, bb.x);
            sf[nt][1] = fmaf(sf[nt][1], SC2, bb.y);
            sf[nt][2] = fmaf(sf[nt][2], SC2, bb.x);
            sf[nt][3] = fmaf(sf[nt][3], SC2, bb.y);
            mt0 = fmaxf(mt0, fmaxf(sf[nt][0], sf[nt][1]));
            mt1 = fmaxf(mt1, fmaxf(sf[nt][2], sf[nt][3]));
        }
        mt0 = fmaxf(mt0, __shfl_xor_sync(0xffffffffu, mt0, 1));
        mt0 = fmaxf(mt0, __shfl_xor_sync(0xffffffffu, mt0, 2));
        mt1 = fmaxf(mt1, __shfl_xor_sync(0xffffffffu, mt1, 1));
        mt1 = fmaxf(mt1, __shfl_xor_sync(0xffffffffu, mt1, 2));

        const float mn0 = fmaxf(m0, mt0);
        const float mn1 = fmaxf(m1, mt1);
        const float alpha0 = ex2f(m0 - mn0);
        const float alpha1 = ex2f(m1 - mn1);
        m0 = mn0; m1 = mn1;

        float ls0 = 0.0f, ls1 = 0.0f;
        uint32_t pa[4][4];
#pragma unroll
        for (int nt = 0; nt < 8; nt++) {
            float p0 = ex2f(sf[nt][0] - mn0);
            float p1 = ex2f(sf[nt][1] - mn0);
            float p2 = ex2f(sf[nt][2] - mn1);
            float p3 = ex2f(sf[nt][3] - mn1);
            ls0 += p0 + p1;
            ls1 += p2 + p3;
            const int kt = nt >> 1;
            const int hi = (nt & 1) ? 2 : 0;
            pa[kt][hi + 0] = packh2(p0, p1);
            pa[kt][hi + 1] = packh2(p2, p3);
        }
        l0 = l0 * alpha0 + ls0;
        l1 = l1 * alpha1 + ls1;
#pragma unroll
        for (int nt = 0; nt < 8; nt++) {
            of[nt][0] *= alpha0;
            of[nt][1] *= alpha0;
            of[nt][2] *= alpha1;
            of[nt][3] *= alpha1;
        }

        // ---- prefetch V(i+1) ----
        uint32_t vreg[8];
        if (have_next) {
#pragma unroll
            for (int j = 0; j < 8; j++) {
                const int key = krow + j * 8;
                const float* vp = qkv + (size_t)(b * SEQN + kb_next + key) * (3 * DIMC) + 2 * DIMC + h * DH + dcol;
                float2 vv = *(const float2*)vp;
                vreg[j] = packh2(vv.x, vv.y);
            }
        }

        // ---- O += P V on buffer cur ----
        const uint32_t vb = vsmem + (uint32_t)(cur * 64 * 72 * 2);
#pragma unroll
        for (int kt = 0; kt < 4; kt++) {
#pragma unroll
            for (int c = 0; c < 8; c += 2) {
                uint32_t r0, r1, r2, r3;
                uint32_t addr = vb + (uint32_t)(((16 * kt + lr) * 72 + lc + 8 * c) * 2);
                ldsm_x4_t(r0, r1, r2, r3, addr);
                mma16816(of[c],     pa[kt], r0, r1);
                mma16816(of[c + 1], pa[kt], r2, r3);
            }
        }

        // store V(i+1), mask(i+1)
        if (have_next) {
#pragma unroll
            for (int j = 0; j < 8; j++)
                *(uint32_t*)&Vs[nxt][krow + j * 8][dcol] = vreg[j];
            if (t < 64) mb[nxt][t] = mreg;
        }
        __syncthreads();
    }

    // ---- epilogue ----
    l0 += __shfl_xor_sync(0xffffffffu, l0, 1);
    l0 += __shfl_xor_sync(0xffffffffu, l0, 2);
    l1 += __shfl_xor_sync(0xffffffffu, l1, 1);
    l1 += __shfl_xor_sync(0xffffffffu, l1, 2);
    const float inv0 = 1.0f / l0;
    const float inv1 = 1.0f / l1;

    const int qr = qbase + w * 16 + g;
    float* o0 = xout + ((size_t)(b * SEQN + qr) * HEADS + h) * DH;
    float* o8 = xout + ((size_t)(b * SEQN + qr + 8) * HEADS + h) * DH;
#pragma unroll
    for (int nt = 0; nt < 8; nt++) {
        float2 v0, v1;
        v0.x = of[nt][0] * inv0; v0.y = of[nt][1] * inv0;
        v1.x = of[nt][2] * inv1; v1.y = of[nt][3] * inv1;
        *(float2*)(o0 + 8 * nt + 2 * tg) = v0;
        *(float2*)(o8 + 8 * nt + 2 * tg) = v1;
    }
}

// ---------------------------------------------------------------------------
extern "C" void kernel_launch(void* const* d_in, const int* in_sizes, int n_in,
                              void* d_out, int out_size)
{
    const float* x     = (const float*)d_in[0];
    const float* Wqkv  = (const float*)d_in[1];
    const float* Wfc   = (const float*)d_in[2];
    const float* bfc   = (const float*)d_in[3];
    const int*   pmask = (const int*)d_in[4];
    float* out = (float*)d_out;

    float *qkv, *xa;
    cudaGetSymbolAddress((void**)&qkv, g_qkv);
    cudaGetSymbolAddress((void**)&xa, g_x);

    const int M = BATCHB * SEQN;  // 8192
    const int GEMM_SMEM = 4 * TILE_U32 * (int)sizeof(uint32_t);  // 73728

    cudaFuncSetAttribute(gemm_nt_tf32, cudaFuncAttributeMaxDynamicSharedMemorySize, GEMM_SMEM);

    // 1) qkv = X @ Wqkv^T   (M x 3072), TF32 tensor cores, pipelined
    gemm_nt_tf32<<<dim3(3 * DIMC / 128, M / 128), 256, GEMM_SMEM>>>(x, Wqkv, qkv, nullptr, M, 3 * DIMC, DIMC);

    // 2) flash attention (fp16 tensor cores, pipelined) -> xa
    attn_fa16<<<dim3(SEQN / 128, HEADS, BATCHB), 256>>>(qkv, pmask, xa);

    // 3) out = xa @ Wfc^T + b_fc, TF32 tensor cores, pipelined
    gemm_nt_tf32<<<dim3(DIMC / 128, M / 128), 256, GEMM_SMEM>>>(xa, Wfc, out, bfc, M, DIMC, DIMC);
}

// round 8
// speedup vs baseline: 2.3461x; 2.3461x over previous
#include <cuda_runtime.h>
#include <cuda_fp16.h>
#include <cstdint>

#define DIMC 1024
#define HEADS 16
#define DH 64
#define BATCHB 4
#define SEQN 2048
#define MROWS (BATCHB * SEQN)
#define SCALE 0.125f
#define LOG2E 1.4426950408889634f

// Scratch (no allocations allowed)
__device__ __half g_xh[(size_t)MROWS * DIMC];
__device__ __half g_wqh[(size_t)3 * DIMC * DIMC];
__device__ __half g_wfh[(size_t)DIMC * DIMC];
__device__ __half g_qkvh[(size_t)MROWS * 3 * DIMC];
__device__ __half g_xah[(size_t)MROWS * DIMC];

// ---------------- PTX helpers ----------------
__device__ __forceinline__ void mma16816(float* d, const uint32_t* a, uint32_t b0, uint32_t b1) {
    asm volatile(
        "mma.sync.aligned.m16n8k16.row.col.f32.f16.f16.f32 "
        "{%0,%1,%2,%3}, {%4,%5,%6,%7}, {%8,%9}, {%0,%1,%2,%3};"
        : "+f"(d[0]), "+f"(d[1]), "+f"(d[2]), "+f"(d[3])
        : "r"(a[0]), "r"(a[1]), "r"(a[2]), "r"(a[3]),
          "r"(b0), "r"(b1));
}
__device__ __forceinline__ void ldsm_x4(uint32_t* r, uint32_t addr) {
    asm volatile("ldmatrix.sync.aligned.m8n8.x4.shared.b16 {%0,%1,%2,%3}, [%4];"
                 : "=r"(r[0]), "=r"(r[1]), "=r"(r[2]), "=r"(r[3]) : "r"(addr));
}
__device__ __forceinline__ void ldsm_x4_t(uint32_t& r0, uint32_t& r1, uint32_t& r2, uint32_t& r3,
                                          uint32_t addr) {
    asm volatile("ldmatrix.sync.aligned.m8n8.x4.trans.shared.b16 {%0,%1,%2,%3}, [%4];"
                 : "=r"(r0), "=r"(r1), "=r"(r2), "=r"(r3) : "r"(addr));
}
__device__ __forceinline__ float ex2f(float x) {
    float y;
    asm("ex2.approx.ftz.f32 %0, %1;" : "=f"(y) : "f"(x));
    return y;
}
__device__ __forceinline__ uint32_t packh2(float lo, float hi) {
    __half2 h = __floats2half2_rn(lo, hi);
    return *(uint32_t*)&h;
}
__device__ __forceinline__ void cp16(uint32_t dst, const void* src) {
    asm volatile("cp.async.cg.shared.global [%0], [%1], 16;" :: "r"(dst), "l"(src) : "memory");
}
#define CP_COMMIT() asm volatile("cp.async.commit_group;" ::: "memory")
#define CP_WAIT0()  asm volatile("cp.async.wait_group 0;" ::: "memory")
#define CP_WAIT1()  asm volatile("cp.async.wait_group 1;" ::: "memory")

// ---------------------------------------------------------------------------
// fp32 -> fp16 conversion pass (grid-stride-free exact cover; n % 1024 == 0)
// ---------------------------------------------------------------------------
__global__ __launch_bounds__(256) void cvt_fp16(const float* __restrict__ in,
                                                __half* __restrict__ out, int n)
{
    int i = (blockIdx.x * 256 + threadIdx.x) * 4;
    if (i >= n) return;
    float4 v = *(const float4*)(in + i);
    uint2 o;
    o.x = packh2(v.x, v.y);
    o.y = packh2(v.z, v.w);
    *(uint2*)(out + i) = o;
}

// ---------------------------------------------------------------------------
// fp16 GEMM: C[m,n] = sum_k A[m,k]*B[n,k] (+bias). K = 1024 fixed.
// Block 128x128, BK=32, 256 threads (8 warps as 2m x 4n), warp tile 64x32.
// 3-stage cp.async pipeline; smem per stage: A[128][40] | B[128][40] halves.
// Fragments via ldmatrix.x4 (80B row stride -> conflict-free phases).
// ---------------------------------------------------------------------------
#define GST     20480   // bytes per stage (A 10240 + B 10240)
#define GSMEM   (3 * GST)

template <bool OUT_HALF>
__global__ __launch_bounds__(256) void gemm_h(const __half* __restrict__ A,
                                              const __half* __restrict__ B,
                                              void* __restrict__ Cout,
                                              const float* __restrict__ bias,
                                              int N)
{
    extern __shared__ unsigned char sm[];
    const uint32_t smb = (uint32_t)__cvta_generic_to_shared(sm);
    const int tid  = threadIdx.x;
    const int wid  = tid >> 5;
    const int lane = tid & 31;
    const int g    = lane >> 2;
    const int tg   = lane & 3;
    const int bm   = blockIdx.y * 128;
    const int bn   = blockIdx.x * 128;
    const int wm   = (wid >> 2) * 64;
    const int wn   = (wid & 3) * 32;

    // staging map: thread -> row (tid>>1), two 16B chunks at (tid&1)*2
    const int r   = tid >> 1;
    const int ch0 = (tid & 1) * 2;
    const __half* Ap = A + (size_t)(bm + r) * DIMC + ch0 * 8;
    const __half* Bp = B + (size_t)(bn + r) * DIMC + ch0 * 8;
    const uint32_t dA = smb + (uint32_t)(r * 80 + ch0 * 16);
    const uint32_t dB = dA + 10240;

    float acc[4][4][4];
#pragma unroll
    for (int mt = 0; mt < 4; mt++)
#pragma unroll
        for (int nt = 0; nt < 4; nt++)
#pragma unroll
            for (int i = 0; i < 4; i++) acc[mt][nt][i] = 0.0f;

    // prologue: stage chunks 0,1
#pragma unroll
    for (int c = 0; c < 2; c++) {
        cp16(dA + c * GST,      Ap + c * 32);
        cp16(dA + c * GST + 16, Ap + c * 32 + 8);
        cp16(dB + c * GST,      Bp + c * 32);
        cp16(dB + c * GST + 16, Bp + c * 32 + 8);
        CP_COMMIT();
    }

    // per-lane ldmatrix base offsets (stage-relative)
    // A x4: lanes 0-15 -> rows 0-15 @k0, lanes 16-31 -> rows 0-15 @k+8
    const uint32_t aoff = (uint32_t)((wm + (lane & 15)) * 80 + (lane >> 4) * 16);
    // B x4: m0 lanes0-7 n0-7@k0, m1 8-15 n0-7@k8, m2 16-23 n8-15@k0, m3 24-31 n8-15@k8
    const uint32_t boff = (uint32_t)(10240 + (wn + (lane & 7) + (lane >> 4) * 8) * 80 +
                                     ((lane >> 3) & 1) * 16);

    for (int c = 0; c < 32; c++) {
        const int s = c % 3;
        if (c == 31) { CP_WAIT0(); } else { CP_WAIT1(); }
        __syncthreads();
        if (c + 2 < 32) {
            const int sn = (c + 2) % 3;
            const __half* sa = Ap + (c + 2) * 32;
            const __half* sb = Bp + (c + 2) * 32;
            cp16(dA + sn * GST,      sa);
            cp16(dA + sn * GST + 16, sa + 8);
            cp16(dB + sn * GST,      sb);
            cp16(dB + sn * GST + 16, sb + 8);
            CP_COMMIT();
        }
        const uint32_t sb32 = smb + (uint32_t)(s * GST);
#pragma unroll
        for (int ks = 0; ks < 2; ks++) {
            uint32_t af[4][4], bf[2][4];
#pragma unroll
            for (int mt = 0; mt < 4; mt++)
                ldsm_x4(af[mt], sb32 + aoff + mt * 1280 + ks * 32);
#pragma unroll
            for (int p = 0; p < 2; p++)
                ldsm_x4(bf[p], sb32 + boff + p * 1280 + ks * 32);
#pragma unroll
            for (int mt = 0; mt < 4; mt++)
#pragma unroll
                for (int nt = 0; nt < 4; nt++)
                    mma16816(acc[mt][nt], af[mt],
                             bf[nt >> 1][(nt & 1) * 2], bf[nt >> 1][(nt & 1) * 2 + 1]);
        }
    }

    // epilogue
#pragma unroll
    for (int mt = 0; mt < 4; mt++) {
#pragma unroll
        for (int nt = 0; nt < 4; nt++) {
            const int row0 = bm + wm + mt * 16 + g;
            const int col  = bn + wn + nt * 8 + 2 * tg;
            if (OUT_HALF) {
                __half* C = (__half*)Cout;
                *(uint32_t*)&C[(size_t)row0 * N + col]       = packh2(acc[mt][nt][0], acc[mt][nt][1]);
                *(uint32_t*)&C[(size_t)(row0 + 8) * N + col] = packh2(acc[mt][nt][2], acc[mt][nt][3]);
            } else {
                float* C = (float*)Cout;
                float b0 = 0.0f, b1 = 0.0f;
                if (bias != nullptr) { b0 = bias[col]; b1 = bias[col + 1]; }
                float2 v0, v1;
                v0.x = acc[mt][nt][0] + b0; v0.y = acc[mt][nt][1] + b1;
                v1.x = acc[mt][nt][2] + b0; v1.y = acc[mt][nt][3] + b1;
                *(float2*)(C + (size_t)row0 * N + col)       = v0;
                *(float2*)(C + (size_t)(row0 + 8) * N + col) = v1;
            }
        }
    }
}

// ---------------------------------------------------------------------------
// Flash attention, fp16 MMA, fp16 qkv input (cp.async staging), fp16 output.
// Block = (b, h, 128 q-rows). 8 warps x 16 q-rows. 64-key tiles.
// ---------------------------------------------------------------------------
__global__ __launch_bounds__(256, 2) void attn_fa16(const __half* __restrict__ qkvh,
                                                    const int* __restrict__ pmask,
                                                    __half* __restrict__ xout)
{
    __shared__ __half Ks[64][72];
    __shared__ __half Vs[64][72];
    __shared__ float  mb[64];

    const int t    = threadIdx.x;
    const int w    = t >> 5;
    const int lane = t & 31;
    const int g    = lane >> 2;
    const int tg   = lane & 3;
    const int h    = blockIdx.y;
    const int b    = blockIdx.z;
    const int qbase = blockIdx.x * 128;

    const float SC2 = SCALE * LOG2E;

    // ---- Q fragments: direct fp16 loads, held in registers ----
    uint32_t qa[4][4];
    {
        const int qr = b * SEQN + qbase + w * 16 + g;
        const __half* q0 = qkvh + (size_t)qr * (3 * DIMC) + h * DH;
        const __half* q8 = q0 + (size_t)8 * (3 * DIMC);
#pragma unroll
        for (int kt = 0; kt < 4; kt++) {
            qa[kt][0] = *(const uint32_t*)(q0 + kt * 16 + 2 * tg);
            qa[kt][1] = *(const uint32_t*)(q8 + kt * 16 + 2 * tg);
            qa[kt][2] = *(const uint32_t*)(q0 + kt * 16 + 8 + 2 * tg);
            qa[kt][3] = *(const uint32_t*)(q8 + kt * 16 + 8 + 2 * tg);
        }
    }

    const int lr = ((lane >> 3) & 1) * 8 + (lane & 7);
    const int lc = (lane >> 4) * 8;
    const uint32_t vbase = (uint32_t)__cvta_generic_to_shared(&Vs[0][0]);
    const uint32_t kbase = (uint32_t)__cvta_generic_to_shared(&Ks[0][0]);

    float m0 = -1e30f, m1 = -1e30f, l0 = 0.0f, l1 = 0.0f;
    float of[8][4];
#pragma unroll
    for (int nt = 0; nt < 8; nt++)
#pragma unroll
        for (int i = 0; i < 4; i++) of[nt][i] = 0.0f;

    // cp.async staging map: row = t>>2, chunks (t&3)*2 .. +1 (16B each)
    const int rk  = t >> 2;
    const int chk = (t & 3) * 2;
    const uint32_t dK = kbase + (uint32_t)(rk * 144 + chk * 16);
    const uint32_t dV = vbase + (uint32_t)(rk * 144 + chk * 16);

    for (int kb = 0; kb < SEQN; kb += 64) {
        __syncthreads();
        {
            const __half* kp = qkvh + (size_t)(b * SEQN + kb + rk) * (3 * DIMC) + DIMC + h * DH + chk * 8;
            cp16(dK,      kp);
            cp16(dK + 16, kp + 8);
            cp16(dV,      kp + DIMC);
            cp16(dV + 16, kp + DIMC + 8);
            CP_COMMIT();
        }
        if (t < 64) mb[t] = (pmask[b * SEQN + kb + t] > 0) ? -1e9f : 0.0f;
        CP_WAIT0();
        __syncthreads();

        // ---- S = Q K^T (16 x 64 per warp) ----
        float sf[8][4];
#pragma unroll
        for (int nt = 0; nt < 8; nt++)
#pragma unroll
            for (int i = 0; i < 4; i++) sf[nt][i] = 0.0f;
#pragma unroll
        for (int kt = 0; kt < 4; kt++) {
#pragma unroll
            for (int nt = 0; nt < 8; nt++) {
                uint32_t kb0 = *(const uint32_t*)&Ks[8 * nt + g][16 * kt + 2 * tg];
                uint32_t kb1 = *(const uint32_t*)&Ks[8 * nt + g][16 * kt + 2 * tg + 8];
                mma16816(sf[nt], qa[kt], kb0, kb1);
            }
        }

        // ---- softmax (base-2) ----
        float mt0 = -1e30f, mt1 = -1e30f;
#pragma unroll
        for (int nt = 0; nt < 8; nt++) {
            float2 bb = *(const float2*)&mb[8 * nt + 2 * tg];
            sf[nt][0] = fmaf(sf[nt][0], SC2, bb.x);
            sf[nt][1] = fmaf(sf[nt][1], SC2, bb.y);
            sf[nt][2] = fmaf(sf[nt][2], SC2, bb.x);
            sf[nt][3] = fmaf(sf[nt][3], SC2, bb.y);
            mt0 = fmaxf(mt0, fmaxf(sf[nt][0], sf[nt][1]));
            mt1 = fmaxf(mt1, fmaxf(sf[nt][2], sf[nt][3]));
        }
        mt0 = fmaxf(mt0, __shfl_xor_sync(0xffffffffu, mt0, 1));
        mt0 = fmaxf(mt0, __shfl_xor_sync(0xffffffffu, mt0, 2));
        mt1 = fmaxf(mt1, __shfl_xor_sync(0xffffffffu, mt1, 1));
        mt1 = fmaxf(mt1, __shfl_xor_sync(0xffffffffu, mt1, 2));

        const float mn0 = fmaxf(m0, mt0);
        const float mn1 = fmaxf(m1, mt1);
        const float alpha0 = ex2f(m0 - mn0);
        const float alpha1 = ex2f(m1 - mn1);
        m0 = mn0; m1 = mn1;

        float ls0 = 0.0f, ls1 = 0.0f;
        uint32_t pa[4][4];
#pragma unroll
        for (int nt = 0; nt < 8; nt++) {
            float p0 = ex2f(sf[nt][0] - mn0);
            float p1 = ex2f(sf[nt][1] - mn0);
            float p2 = ex2f(sf[nt][2] - mn1);
            float p3 = ex2f(sf[nt][3] - mn1);
            ls0 += p0 + p1;
            ls1 += p2 + p3;
            const int kt = nt >> 1;
            const int hi = (nt & 1) ? 2 : 0;
            pa[kt][hi + 0] = packh2(p0, p1);
            pa[kt][hi + 1] = packh2(p2, p3);
        }
        l0 = l0 * alpha0 + ls0;
        l1 = l1 * alpha1 + ls1;
#pragma unroll
        for (int nt = 0; nt < 8; nt++) {
            of[nt][0] *= alpha0;
            of[nt][1] *= alpha0;
            of[nt][2] *= alpha1;
            of[nt][3] *= alpha1;
        }

        // ---- O += P V ----
#pragma unroll
        for (int kt = 0; kt < 4; kt++) {
#pragma unroll
            for (int c = 0; c < 8; c += 2) {
                uint32_t r0, r1, r2, r3;
                uint32_t addr = vbase + (uint32_t)(((16 * kt + lr) * 72 + lc + 8 * c) * 2);
                ldsm_x4_t(r0, r1, r2, r3, addr);
                mma16816(of[c],     pa[kt], r0, r1);
                mma16816(of[c + 1], pa[kt], r2, r3);
            }
        }
    }

    // ---- epilogue (fp16 out) ----
    l0 += __shfl_xor_sync(0xffffffffu, l0, 1);
    l0 += __shfl_xor_sync(0xffffffffu, l0, 2);
    l1 += __shfl_xor_sync(0xffffffffu, l1, 1);
    l1 += __shfl_xor_sync(0xffffffffu, l1, 2);
    const float inv0 = 1.0f / l0;
    const float inv1 = 1.0f / l1;

    const int qr = qbase + w * 16 + g;
    __half* o0 = xout + ((size_t)(b * SEQN + qr) * HEADS + h) * DH;
    __half* o8 = xout + ((size_t)(b * SEQN + qr + 8) * HEADS + h) * DH;
#pragma unroll
    for (int nt = 0; nt < 8; nt++) {
        *(uint32_t*)&o0[8 * nt + 2 * tg] = packh2(of[nt][0] * inv0, of[nt][1] * inv0);
        *(uint32_t*)&o8[8 * nt + 2 * tg] = packh2(of[nt][2] * inv1, of[nt][3] * inv1);
    }
}

// ---------------------------------------------------------------------------
extern "C" void kernel_launch(void* const* d_in, const int* in_sizes, int n_in,
                              void* d_out, int out_size)
{
    const float* x     = (const float*)d_in[0];
    const float* Wqkv  = (const float*)d_in[1];
    const float* Wfc   = (const float*)d_in[2];
    const float* bfc   = (const float*)d_in[3];
    const int*   pmask = (const int*)d_in[4];
    float* out = (float*)d_out;

    __half *xh, *wqh, *wfh, *qkvh, *xah;
    cudaGetSymbolAddress((void**)&xh, g_xh);
    cudaGetSymbolAddress((void**)&wqh, g_wqh);
    cudaGetSymbolAddress((void**)&wfh, g_wfh);
    cudaGetSymbolAddress((void**)&qkvh, g_qkvh);
    cudaGetSymbolAddress((void**)&xah, g_xah);

    cudaFuncSetAttribute(gemm_h<true>,  cudaFuncAttributeMaxDynamicSharedMemorySize, GSMEM);
    cudaFuncSetAttribute(gemm_h<false>, cudaFuncAttributeMaxDynamicSharedMemorySize, GSMEM);

    // 0) fp32 -> fp16 conversion passes
    cvt_fp16<<<(MROWS * DIMC) / 1024, 256>>>(x, xh, MROWS * DIMC);
    cvt_fp16<<<(3 * DIMC * DIMC) / 1024, 256>>>(Wqkv, wqh, 3 * DIMC * DIMC);
    cvt_fp16<<<(DIMC * DIMC) / 1024, 256>>>(Wfc, wfh, DIMC * DIMC);

    // 1) qkv = X @ Wqkv^T  (8192 x 3072), fp16 MMA, fp16 out
    gemm_h<true><<<dim3(3 * DIMC / 128, MROWS / 128), 256, GSMEM>>>(xh, wqh, qkvh, nullptr, 3 * DIMC);

    // 2) flash attention (fp16 in/out) -> xah
    attn_fa16<<<dim3(SEQN / 128, HEADS, BATCHB), 256>>>(qkvh, pmask, xah);

    // 3) out = xa @ Wfc^T + b_fc  (8192 x 1024), fp16 MMA, fp32 out
    gemm_h<false><<<dim3(DIMC / 128, MROWS / 128), 256, GSMEM>>>(xah, wfh, out, bfc, DIMC);
}